// round 9
// baseline (speedup 1.0000x reference)
#include <cuda_runtime.h>
#include <cstdint>

#define KTOT   4194304
#define CHUNK  64                       // outputs per chain
#define WARM   128                      // warmup (redundant) steps per chain
#define TS     32                       // steps per tile
#define NT     6                        // (WARM+CHUNK)/TS tiles
#define WTILES 4                        // WARM/TS warmup tiles
#define NCH    (KTOT / CHUNK)           // 65536 chains (1 per thread)
#define WPB    2                        // warps per block
#define TPB    (WPB * 32)
#define NBLK   (NCH / 32 / WPB)         // 1024 blocks
#define PITCH  34                       // row pitch in floats (8B-aligned, conflict-free LDS.64)
#define ROWS   34                       // rows per parity buffer (32 + 2 shift slots)

__device__ __forceinline__ float frcp_ap(float x) {
    float r; asm("rcp.approx.ftz.f32 %0, %1;" : "=f"(r) : "f"(x)); return r;
}
__device__ __forceinline__ float fsqrt_ap(float x) {
    float r; asm("sqrt.approx.f32 %0, %1;" : "=f"(r) : "f"(x)); return r;
}
__device__ __forceinline__ void cp_async8(uint32_t dst, const float* src) {
    asm volatile("cp.async.ca.shared.global [%0], [%1], 8;" :: "r"(dst), "l"(src));
}
#define CP_COMMIT() asm volatile("cp.async.commit_group;" ::: "memory")
#define CP_WAIT1()  asm volatile("cp.async.wait_group 1;"  ::: "memory")
#define CP_WAIT0()  asm volatile("cp.async.wait_group 0;"  ::: "memory")

struct P { float nu, Amu, As, bmu, Bs, wmu, ws; };

__device__ __forceinline__ void gas_step(const float y, float& mu, float& s2, const P& p) {
    // scale*r = (nu+1)*s2*r / (nu*s2 + r^2): one rcp, 10 fma-pipe ops
    const float r_  = y - mu;
    const float rr  = r_ * r_;
    const float d   = fmaf(p.nu, s2, rr);
    const float q   = frcp_ap(d);
    const float s2r = s2 * r_;
    const float mb  = fmaf(p.bmu, mu, p.wmu);   // off critical path
    const float sb  = fmaf(p.Bs,  s2, p.ws);    // off critical path
    const float N   = s2r * q;
    mu = fmaf(p.Amu, N, mb);
    s2 = fmaf(p.As, N * r_, sb);
}

// Initial burst staging of tile tau (rows 0..31 = chains wcb..wcb+31).
// lane -> row r0=lane>>4 (+2 per k), col=(lane&15)*2. 16 cp.async8 per lane.
template<bool GUARD>
__device__ __forceinline__ void stage_init(
    const int tau, const int wcb, const int lane,
    const float* __restrict__ y, float* buf)
{
    const int r0  = lane >> 4;
    const int col = (lane & 15) * 2;
    uint32_t dst = (uint32_t)__cvta_generic_to_shared(buf + r0 * PITCH + col);
    const int gbase = (wcb + r0) * CHUNK - WARM + tau * TS + col;
    #pragma unroll
    for (int k = 0; k < 16; ++k) {
        int g = gbase + k * (2 * CHUNK);
        if (GUARD) g = max(g, 0);      // pre-t0 slots: skipped in compute anyway
        cp_async8(dst + (uint32_t)(k * (2 * PITCH * 4)), y + g);
    }
    CP_COMMIT();
}

// Stage the single NEW row for tile t2 into its parity buffer:
// row 31+(t2>>1), content = chain wcb+31, steps [ (wcb+31)*CHUNK - WARM + t2*TS, +32 ).
// Only 16 lanes issue (128B total); ALL lanes commit to keep group counts aligned.
__device__ __forceinline__ void stage_row(
    const int t2, const int wcb, const int lane,
    const float* __restrict__ y, float* buf)
{
    const int row = 31 + (t2 >> 1);
    if (lane < 16) {
        const int col = lane * 2;
        uint32_t dst = (uint32_t)__cvta_generic_to_shared(buf + row * PITCH + col);
        const int g = (wcb + 31) * CHUNK - WARM + t2 * TS + col;   // always >= 0
        cp_async8(dst, y + g);
    }
    CP_COMMIT();
}

// TS steps of tile tau. rp = &buf[(lane + (tau>>1))][0] (this lane's row view).
// LDS pipelined one pair ahead. EMIT: mu in place (input slot dead), s2 -> sgr.
template<bool GUARD, bool EMIT>
__device__ __forceinline__ void compute_tile(
    const int tau, const int skip,
    float* rp, float* sgr, float& mu, float& s2, const P& p)
{
    float2 cur = *reinterpret_cast<const float2*>(rp);
    #pragma unroll
    for (int j = 0; j < TS / 2; ++j) {
        float2 nxt = cur;
        if (j < TS / 2 - 1)
            nxt = *reinterpret_cast<const float2*>(rp + 2 * j + 2);
        if (GUARD) {
            if (tau * TS + 2 * j     >= skip) gas_step(cur.x, mu, s2, p);
            if (tau * TS + 2 * j + 1 >= skip) gas_step(cur.y, mu, s2, p);
        } else {
            gas_step(cur.x, mu, s2, p);
            const float m0 = mu, v0 = s2;
            gas_step(cur.y, mu, s2, p);
            if (EMIT) {
                *reinterpret_cast<float2*>(rp  + 2 * j) = make_float2(m0, mu);
                *reinterpret_cast<float2*>(sgr + 2 * j) = make_float2(v0, s2);
            }
        }
        cur = nxt;
    }
}

// Coalesced flush: mu from buf rows (chain_row + rowoff), sigma = sqrt(s2) from sg.
__device__ __forceinline__ void flush_tile(
    const int tau, const int wcb, const int lane, const int rowoff,
    const float* buf, const float* sg, float* __restrict__ out)
{
    const int r0  = lane >> 4;
    const int col = (lane & 15) * 2;
    const int ob  = (tau - WTILES) * TS;
    #pragma unroll
    for (int k = 0; k < 16; ++k) {
        const int row = 2 * k + r0;                     // chain row 0..31
        const float2 m = *reinterpret_cast<const float2*>(
            buf + (row + rowoff) * PITCH + col);
        float2 g = *reinterpret_cast<const float2*>(sg + row * PITCH + col);
        g.x = fsqrt_ap(g.x); g.y = fsqrt_ap(g.y);
        const int gi = (wcb + row) * CHUNK + ob + col;
        *reinterpret_cast<float2*>(&out[gi])        = m;
        *reinterpret_cast<float2*>(&out[KTOT + gi]) = g;
    }
}

template<bool GUARD>
__device__ __forceinline__ void run_warp(
    const int wcb, const int lane,
    const float* __restrict__ y, float* __restrict__ out,
    float* bufE, float* bufO, float* sg,
    float mu, float s2, const P& p, const int skip)
{
    stage_init<GUARD>(0, wcb, lane, y, bufE);   // group 0
    stage_init<GUARD>(1, wcb, lane, y, bufO);   // group 1

    #pragma unroll 1
    for (int t = 0; t < NT; ++t) {
        if (t < NT - 1) CP_WAIT1(); else CP_WAIT0();
        __syncwarp();
        float* bp = (t & 1) ? bufO : bufE;
        const int ro = t >> 1;                  // row shift for this tile
        float* rp = bp + (lane + ro) * PITCH;

        // stage the one new row for tile t+2 (groups 2..5), before compute
        if (t + 2 < NT) stage_row(t + 2, wcb, lane, y, bp);

        if (t < WTILES) {
            if (GUARD)
                compute_tile<true,  false>(t, skip, rp, sg, mu, s2, p);
            else
                compute_tile<false, false>(t, skip, rp, sg, mu, s2, p);
        } else {
            float* sgr = sg + lane * PITCH;
            compute_tile<false, true>(t, skip, rp, sgr, mu, s2, p);
            __syncwarp();
            flush_tile(t, wcb, lane, ro, bp, sg, out);
            __syncwarp();   // flush reads done before tile t+1 reuses sg
        }
    }
}

__global__ __launch_bounds__(TPB)
void argas_kernel(
    const float* __restrict__ y,
    const float* __restrict__ p_lastmu,  const float* __restrict__ p_lastsig,
    const float* __restrict__ p_amu,     const float* __restrict__ p_as,
    const float* __restrict__ p_bmu,     const float* __restrict__ p_bs,
    const float* __restrict__ p_wmu,     const float* __restrict__ p_ws,
    const float* __restrict__ p_nu,      const float* __restrict__ p_str,
    float* __restrict__ out)
{
    // per-warp: two parity-shift buffers (34 rows) + sigma staging (32 rows)
    __shared__ float smE[WPB][ROWS][PITCH];
    __shared__ float smO[WPB][ROWS][PITCH];
    __shared__ float smS[WPB][32][PITCH];

    const int warp  = threadIdx.x >> 5;
    const int lane  = threadIdx.x & 31;
    const int wcb   = (blockIdx.x * WPB + warp) * 32;   // warp's chain base
    const int chain = wcb + lane;

    P p;
    const float nu       = *p_nu;
    const float strength = *p_str;
    const float amu  = (*p_amu) * strength;
    const float as_  = (*p_as)  * strength;
    const float bmu  = *p_bmu;
    const float bs   = *p_bs;
    const float nup1 = nu + 1.0f;
    p.nu  = nu;
    p.Amu = bmu * amu * nup1;
    p.As  = bs  * as_ * nup1;
    p.bmu = bmu;
    p.Bs  = bs * (1.0f - as_);
    p.wmu = *p_wmu;
    p.ws  = *p_ws;

    const float mu0 = *p_lastmu;   // chains whose warmup reaches before idx 0
    const float s20 = *p_lastsig;  // skip those steps; they start exact.

    const int skip = WARM - chain * CHUNK;   // >0 only for chains 0,1 (warp 0)

    if (wcb == 0)
        run_warp<true >(wcb, lane, y, out,
                        &smE[warp][0][0], &smO[warp][0][0], &smS[warp][0][0],
                        mu0, s20, p, skip);
    else
        run_warp<false>(wcb, lane, y, out,
                        &smE[warp][0][0], &smO[warp][0][0], &smS[warp][0][0],
                        mu0, s20, p, skip);
}

extern "C" void kernel_launch(void* const* d_in, const int* in_sizes, int n_in,
                              void* d_out, int out_size) {
    const float* y = (const float*)d_in[0];
    argas_kernel<<<NBLK, TPB>>>(
        y,
        (const float*)d_in[1],  (const float*)d_in[2],
        (const float*)d_in[3],  (const float*)d_in[4],
        (const float*)d_in[5],  (const float*)d_in[6],
        (const float*)d_in[7],  (const float*)d_in[8],
        (const float*)d_in[9],  (const float*)d_in[10],
        (float*)d_out);
}